// round 7
// baseline (speedup 1.0000x reference)
#include <cuda_runtime.h>
#include <math.h>

typedef unsigned int u32;
typedef unsigned long long u64;

#define NLEV 16
#define HSIZE (1u << 19)
#define HMASK (HSIZE - 1u)
#define NPTS (4096 * 128)

// dynamic-smem float offsets
#define OFF_WIN  0
#define OFF_WOUT 2048
#define OFF_W1   3072
#define OFF_W2   4032
#define OFF_W3   8128
#define OFF_EA   8320
#define OFF_EB   (8320 + 128 * 33)
#define SMEM_FLOATS (8320 + 2 * 128 * 33)
#define SMEM_BYTES (SMEM_FLOATS * 4)

struct Consts { float res[NLEV]; };

// ---------- packed f32x2 helpers ----------
__device__ __forceinline__ u64 pk2(float a, float b) {
    u64 r; asm("mov.b64 %0,{%1,%2};" : "=l"(r) : "f"(a), "f"(b)); return r;
}
__device__ __forceinline__ void up2(u64 v, float& a, float& b) {
    asm("mov.b64 {%0,%1},%2;" : "=f"(a), "=f"(b) : "l"(v));
}
__device__ __forceinline__ u64 f2fma(u64 a, u64 b, u64 c) {
    u64 d; asm("fma.rn.f32x2 %0,%1,%2,%3;" : "=l"(d) : "l"(a), "l"(b), "l"(c)); return d;
}

// encode one ray's point: 16 levels of 8 gathers + trilerp -> Erow[0..31]
__device__ __forceinline__ void encode_ray(
    float px, float py, float pz, const float* __restrict__ table,
    const Consts& cc, float* __restrict__ Erow)
{
    #pragma unroll 1
    for (int l = 0; l < NLEV; l++) {
        const float r = cc.res[l];
        const float2* tab = (const float2*)table + (size_t)l * HSIZE;
        const float X = px * r, Y = py * r, Z = pz * r;
        const float fx = floorf(X), fy = floorf(Y), fz = floorf(Z);
        const float ax = X - fx, ay = Y - fy, az = Z - fz;
        const u32 ix = (u32)fx, iy = (u32)fy, iz = (u32)fz;
        const u32 hx0 = ix, hx1 = ix + 1u;
        const u32 hy0 = iy * 2654435761u, hy1 = hy0 + 2654435761u;
        const u32 hz0 = iz * 805459861u,  hz1 = hz0 + 805459861u;

        float2 tv[8];
        #pragma unroll
        for (int c = 0; c < 8; c++) {
            const u32 hx = (c & 4) ? hx1 : hx0;
            const u32 hy = (c & 2) ? hy1 : hy0;
            const u32 hz = (c & 1) ? hz1 : hz0;
            tv[c] = __ldg(tab + ((hx ^ hy ^ hz) & HMASK));
        }
        const float bx = 1.f - ax, by = 1.f - ay, bz = 1.f - az;
        float a0 = 0.f, a1 = 0.f;
        #pragma unroll
        for (int c = 0; c < 8; c++) {
            const float w = ((c & 4) ? ax : bx) * ((c & 2) ? ay : by) * ((c & 1) ? az : bz);
            a0 = fmaf(w, tv[c].x, a0);
            a1 = fmaf(w, tv[c].y, a1);
        }
        Erow[2 * l]     = a0;
        Erow[2 * l + 1] = a1;
    }
}

// fused: encode (smem-staged) -> density MLP (2pt weight-shared) -> scan -> rgb
__global__ void __launch_bounds__(128, 3) fused_point_kernel(
    const float* __restrict__ xyz, const float* __restrict__ delta,
    const float* __restrict__ table,
    const float* __restrict__ w_in, const float* __restrict__ w_out,
    const float* __restrict__ rw1, const float* __restrict__ rw2,
    const float* __restrict__ rw3, float4* __restrict__ out, Consts cc,
    float offset)
{
    extern __shared__ float dsm[];
    __shared__ float wsumA[4], wsumB[4];
    const int t = threadIdx.x;
    for (int i = t; i < 8320; i += 128) {
        float v;
        if (i < 2048)      v = w_in[i];
        else if (i < 3072) v = w_out[i - 2048];
        else if (i < 4032) v = rw1[i - 3072];
        else if (i < 8128) v = rw2[i - 4032];
        else               v = rw3[i - 8128];
        dsm[i] = v;
    }
    __syncthreads();

    const int pA = blockIdx.x * 256 + t;   // ray A
    const int pB = pA + 128;               // ray B
    float* EArow = dsm + OFF_EA + t * 33;
    float* EBrow = dsm + OFF_EB + t * 33;

    // ---- phase 1: encode both points into smem (thread-private rows) ----
    {
        const float pxA = __ldg(xyz + 3 * pA), pyA = __ldg(xyz + 3 * pA + 1),
                    pzA = __ldg(xyz + 3 * pA + 2);
        encode_ray(pxA, pyA, pzA, table, cc, EArow);
        const float pxB = __ldg(xyz + 3 * pB), pyB = __ldg(xyz + 3 * pB + 1),
                    pzB = __ldg(xyz + 3 * pB + 2);
        encode_ray(pxB, pyB, pzB, table, cc, EBrow);
    }

    // ---- phase 2: layer 1 (enc @ w_in), both points share weight LDS ----
    u64 hAa[32], hAb[32];
    #pragma unroll
    for (int j = 0; j < 32; j++) { hAa[j] = 0ULL; hAb[j] = 0ULL; }

    #pragma unroll 1
    for (int l = 0; l < NLEV; l++) {
        const float a0A = EArow[2 * l], a1A = EArow[2 * l + 1];
        const float a0B = EBrow[2 * l], a1B = EBrow[2 * l + 1];
        const u64 e0A = pk2(a0A, a0A), e1A = pk2(a1A, a1A);
        const u64 e0B = pk2(a0B, a0B), e1B = pk2(a1B, a1B);
        const u64* r0 = (const u64*)(dsm + OFF_WIN + (2 * l) * 64);
        const u64* r1 = r0 + 32;
        #pragma unroll
        for (int j = 0; j < 32; j += 2) {
            const ulonglong2 wv0 = *(const ulonglong2*)(r0 + j);
            const ulonglong2 wv1 = *(const ulonglong2*)(r1 + j);
            hAa[j]     = f2fma(e1A, wv1.x, f2fma(e0A, wv0.x, hAa[j]));
            hAa[j + 1] = f2fma(e1A, wv1.y, f2fma(e0A, wv0.y, hAa[j + 1]));
            hAb[j]     = f2fma(e1B, wv1.x, f2fma(e0B, wv0.x, hAb[j]));
            hAb[j + 1] = f2fma(e1B, wv1.y, f2fma(e0B, wv0.y, hAb[j + 1]));
        }
    }

    // ---- layer 2: raw = relu(h) @ w_out, two output-halves of 8 ----
    // feats (raw[1..15]) go straight to smem (reusing E rows); only raw[0] kept.
    float d0A = 0.f, d0B = 0.f;
    #pragma unroll 1
    for (int half = 0; half < 2; half++) {
        u64 a2[4], b2[4];
        #pragma unroll
        for (int j = 0; j < 4; j++) { a2[j] = 0ULL; b2[j] = 0ULL; }
        #pragma unroll
        for (int ic = 0; ic < 32; ic++) {
            float vA0, vA1, vB0, vB1;
            up2(hAa[ic], vA0, vA1); up2(hAb[ic], vB0, vB1);
            const u64 e0A = pk2(fmaxf(vA0, 0.f), fmaxf(vA0, 0.f));
            const u64 e1A = pk2(fmaxf(vA1, 0.f), fmaxf(vA1, 0.f));
            const u64 e0B = pk2(fmaxf(vB0, 0.f), fmaxf(vB0, 0.f));
            const u64 e1B = pk2(fmaxf(vB1, 0.f), fmaxf(vB1, 0.f));
            const u64* r0 = (const u64*)(dsm + OFF_WOUT + (2 * ic) * 16 + half * 8);
            const u64* r1 = r0 + 8;
            #pragma unroll
            for (int j = 0; j < 4; j += 2) {
                const ulonglong2 wv0 = *(const ulonglong2*)(r0 + j);
                const ulonglong2 wv1 = *(const ulonglong2*)(r1 + j);
                a2[j]     = f2fma(e1A, wv1.x, f2fma(e0A, wv0.x, a2[j]));
                a2[j + 1] = f2fma(e1A, wv1.y, f2fma(e0A, wv0.y, a2[j + 1]));
                b2[j]     = f2fma(e1B, wv1.x, f2fma(e0B, wv0.x, b2[j]));
                b2[j + 1] = f2fma(e1B, wv1.y, f2fma(e0B, wv0.y, b2[j + 1]));
            }
        }
        #pragma unroll
        for (int j = 0; j < 4; j++) {
            float vA0, vA1, vB0, vB1;
            up2(a2[j], vA0, vA1); up2(b2[j], vB0, vB1);
            const int o = half * 8 + 2 * j;        // output index o, o+1
            if (o == 0) { d0A = vA0; d0B = vB0; }
            else { EArow[o - 1] = vA0; EBrow[o - 1] = vB0; }
            EArow[o] = vA1; EBrow[o] = vB1;        // feats index o+1 -> slot o
        }
    }

    // ---- volume-rendering weights: block-wide exclusive scan per ray ----
    const float ddA = expf(d0A + offset + logf(__ldg(delta + pA)));
    const float ddB = expf(d0B + offset + logf(__ldg(delta + pB)));
    float sA = ddA, sB = ddB;
    const int lane = t & 31, wid = t >> 5;
    #pragma unroll
    for (int o = 1; o < 32; o <<= 1) {
        const float vA = __shfl_up_sync(0xffffffffu, sA, o);
        const float vB = __shfl_up_sync(0xffffffffu, sB, o);
        if (lane >= o) { sA += vA; sB += vB; }
    }
    if (lane == 31) { wsumA[wid] = sA; wsumB[wid] = sB; }
    __syncthreads();
    float prefA = 0.f, prefB = 0.f;
    #pragma unroll
    for (int w = 0; w < 3; w++)
        if (wid > w) { prefA += wsumA[w]; prefB += wsumB[w]; }
    const float exclA = prefA + sA - ddA;
    const float exclB = prefB + sB - ddB;
    const float wgtA = (1.f - expf(-ddA)) * expf(-exclA);
    const float wgtB = (1.f - expf(-ddB)) * expf(-exclB);

    // ---- rgb layer 1: h1 = relu(feats @ rgb_w1), feats from smem ----
    u64 h1A[32], h1B[32];
    #pragma unroll
    for (int j = 0; j < 32; j++) { h1A[j] = 0ULL; h1B[j] = 0ULL; }
    #pragma unroll 1
    for (int i = 0; i < 15; i++) {
        const float fA = EArow[i], fB = EBrow[i];
        const u64 eA = pk2(fA, fA);
        const u64 eB = pk2(fB, fB);
        const u64* row = (const u64*)(dsm + OFF_W1 + i * 64);
        #pragma unroll
        for (int j = 0; j < 32; j += 2) {
            const ulonglong2 wv = *(const ulonglong2*)(row + j);
            h1A[j]     = f2fma(eA, wv.x, h1A[j]);
            h1A[j + 1] = f2fma(eA, wv.y, h1A[j + 1]);
            h1B[j]     = f2fma(eB, wv.x, h1B[j]);
            h1B[j + 1] = f2fma(eB, wv.y, h1B[j + 1]);
        }
    }
    #pragma unroll
    for (int j = 0; j < 32; j++) {
        float v0, v1;
        up2(h1A[j], v0, v1); h1A[j] = pk2(fmaxf(v0, 0.f), fmaxf(v1, 0.f));
        up2(h1B[j], v0, v1); h1B[j] = pk2(fmaxf(v0, 0.f), fmaxf(v1, 0.f));
    }

    // ---- rgb layers 2+3, 8 blocks of 8 outputs ----
    float crA = 0.f, cgA = 0.f, cbA = 0.f;
    float crB = 0.f, cgB = 0.f, cbB = 0.f;
    #pragma unroll 1
    for (int ob = 0; ob < 8; ob++) {
        u64 accA[4], accB[4];
        #pragma unroll
        for (int j = 0; j < 4; j++) { accA[j] = 0ULL; accB[j] = 0ULL; }
        #pragma unroll
        for (int ic = 0; ic < 32; ic++) {
            float vA0, vA1, vB0, vB1;
            up2(h1A[ic], vA0, vA1); up2(h1B[ic], vB0, vB1);
            const u64 e0A = pk2(vA0, vA0), e1A = pk2(vA1, vA1);
            const u64 e0B = pk2(vB0, vB0), e1B = pk2(vB1, vB1);
            const u64* r0 = (const u64*)(dsm + OFF_W2 + (2 * ic) * 64 + ob * 8);
            const u64* r1 = r0 + 32;
            #pragma unroll
            for (int j = 0; j < 4; j += 2) {
                const ulonglong2 wv0 = *(const ulonglong2*)(r0 + j);
                const ulonglong2 wv1 = *(const ulonglong2*)(r1 + j);
                accA[j]     = f2fma(e1A, wv1.x, f2fma(e0A, wv0.x, accA[j]));
                accA[j + 1] = f2fma(e1A, wv1.y, f2fma(e0A, wv0.y, accA[j + 1]));
                accB[j]     = f2fma(e1B, wv1.x, f2fma(e0B, wv0.x, accB[j]));
                accB[j + 1] = f2fma(e1B, wv1.y, f2fma(e0B, wv0.y, accB[j + 1]));
            }
        }
        #pragma unroll
        for (int j = 0; j < 4; j++) {
            float vA0, vA1, vB0, vB1;
            up2(accA[j], vA0, vA1); up2(accB[j], vB0, vB1);
            vA0 = fmaxf(vA0, 0.f); vA1 = fmaxf(vA1, 0.f);
            vB0 = fmaxf(vB0, 0.f); vB1 = fmaxf(vB1, 0.f);
            const float* q = dsm + OFF_W3 + (ob * 8 + 2 * j) * 3;
            crA = fmaf(vA0, q[0], fmaf(vA1, q[3], crA));
            cgA = fmaf(vA0, q[1], fmaf(vA1, q[4], cgA));
            cbA = fmaf(vA0, q[2], fmaf(vA1, q[5], cbA));
            crB = fmaf(vB0, q[0], fmaf(vB1, q[3], crB));
            cgB = fmaf(vB0, q[1], fmaf(vB1, q[4], cgB));
            cbB = fmaf(vB0, q[2], fmaf(vB1, q[5], cbB));
        }
    }

    out[pA] = make_float4(wgtA, 1.f / (1.f + expf(-crA)),
                          1.f / (1.f + expf(-cgA)), 1.f / (1.f + expf(-cbA)));
    out[pB] = make_float4(wgtB, 1.f / (1.f + expf(-crB)),
                          1.f / (1.f + expf(-cgB)), 1.f / (1.f + expf(-cbB)));
}

// pads FIRST: harness has 2 internal launches before ours, so global launch
// idx 5 (ncu -s 5 -c 1) = our 4th launch = fused_point_kernel.
__global__ void pad_kernel() {}

extern "C" void kernel_launch(void* const* d_in, const int* in_sizes, int n_in,
                              void* d_out, int out_size)
{
    const float* xyz   = (const float*)d_in[0];
    const float* delta = (const float*)d_in[1];
    const float* table = (const float*)d_in[2];
    const float* w_in  = (const float*)d_in[3];
    const float* w_out = (const float*)d_in[4];
    const float* rw1   = (const float*)d_in[5];
    const float* rw2   = (const float*)d_in[6];
    const float* rw3   = (const float*)d_in[7];
    float4* out = (float4*)d_out;

    Consts cc;
    const double scale = exp((log(4096.0) - log(16.0)) / 15.0);
    for (int l = 0; l < NLEV; l++)
        cc.res[l] = (float)floor(16.0 * pow(scale, (double)l));
    const float offset = (float)(log(log(1.0 / 0.99)) - log(6.0 - 2.0) - 0.5);

    static int smem_set = 0;
    if (!smem_set) {
        cudaFuncSetAttribute(fused_point_kernel,
                             cudaFuncAttributeMaxDynamicSharedMemorySize,
                             SMEM_BYTES);
        smem_set = 1;
    }

    pad_kernel<<<1, 1>>>();
    pad_kernel<<<1, 1>>>();
    pad_kernel<<<1, 1>>>();
    fused_point_kernel<<<NPTS / 256, 128, SMEM_BYTES>>>(
        xyz, delta, table, w_in, w_out, rw1, rw2, rw3, out, cc, offset);
}

// round 8
// speedup vs baseline: 1.4650x; 1.4650x over previous
#include <cuda_runtime.h>
#include <math.h>

typedef unsigned int u32;
typedef unsigned long long u64;

#define NLEV 16
#define HSIZE (1u << 19)
#define HMASK (HSIZE - 1u)
#define NPTS (4096 * 128)

struct Consts { float res[NLEV]; };

// 67 MB scratch: per-level encoded features, feat-major for coalescing.
// g_enc[l * NPTS + p] = (enc[2l], enc[2l+1]) of point p.
__device__ float2 g_enc[NLEV * NPTS];

// ---------- packed f32x2 helpers ----------
__device__ __forceinline__ u64 pk2(float a, float b) {
    u64 r; asm("mov.b64 %0,{%1,%2};" : "=l"(r) : "f"(a), "f"(b)); return r;
}
__device__ __forceinline__ void up2(u64 v, float& a, float& b) {
    asm("mov.b64 {%0,%1},%2;" : "=f"(a), "=f"(b) : "l"(v));
}
__device__ __forceinline__ u64 f2fma(u64 a, u64 b, u64 c) {
    u64 d; asm("fma.rn.f32x2 %0,%1,%2,%3;" : "=l"(d) : "l"(a), "l"(b), "l"(c)); return d;
}

// ===================== K1: encode (gather-bound) =====================

__device__ __forceinline__ void level_fetch(
    float px, float py, float pz, float r,
    const float2* __restrict__ tab,
    float2 tv[8], float& ax, float& ay, float& az)
{
    const float X = px * r, Y = py * r, Z = pz * r;
    const float fx = floorf(X), fy = floorf(Y), fz = floorf(Z);
    ax = X - fx; ay = Y - fy; az = Z - fz;
    const u32 ix = (u32)fx, iy = (u32)fy, iz = (u32)fz;
    const u32 hx0 = ix, hx1 = ix + 1u;
    const u32 hy0 = iy * 2654435761u, hy1 = hy0 + 2654435761u;
    const u32 hz0 = iz * 805459861u,  hz1 = hz0 + 805459861u;
    #pragma unroll
    for (int c = 0; c < 8; c++) {
        const u32 hx = (c & 4) ? hx1 : hx0;
        const u32 hy = (c & 2) ? hy1 : hy0;
        const u32 hz = (c & 1) ? hz1 : hz0;
        tv[c] = __ldg(tab + ((hx ^ hy ^ hz) & HMASK));
    }
}

__global__ void __launch_bounds__(256, 3) encode_kernel(
    const float* __restrict__ xyz, const float* __restrict__ table, Consts cc)
{
    const int p = blockIdx.x * 256 + threadIdx.x;
    const float px = __ldg(xyz + 3 * p);
    const float py = __ldg(xyz + 3 * p + 1);
    const float pz = __ldg(xyz + 3 * p + 2);

    float2 tvb[2][8];
    float fr[2][3];
    level_fetch(px, py, pz, cc.res[0], (const float2*)table,
                tvb[0], fr[0][0], fr[0][1], fr[0][2]);

    #pragma unroll 2
    for (int l = 0; l < NLEV; l++) {
        const int cur = l & 1, nxt = cur ^ 1;
        if (l + 1 < NLEV)
            level_fetch(px, py, pz, cc.res[l + 1],
                        (const float2*)table + (size_t)(l + 1) * HSIZE,
                        tvb[nxt], fr[nxt][0], fr[nxt][1], fr[nxt][2]);
        const float ax = fr[cur][0], ay = fr[cur][1], az = fr[cur][2];
        const float bx = 1.f - ax, by = 1.f - ay, bz = 1.f - az;
        float a0 = 0.f, a1 = 0.f;
        #pragma unroll
        for (int c = 0; c < 8; c++) {
            const float w = ((c & 4) ? ax : bx) * ((c & 2) ? ay : by) * ((c & 1) ? az : bz);
            a0 = fmaf(w, tvb[cur][c].x, a0);
            a1 = fmaf(w, tvb[cur][c].y, a1);
        }
        g_enc[l * NPTS + p] = make_float2(a0, a1);
    }
}

// ===================== K2: MLP + volrend (FMA/LDS-bound) =====================

// dynamic-smem float offsets
#define OFF_WIN  0
#define OFF_WOUT 2048
#define OFF_W1   3072
#define OFF_W2   4032
#define OFF_W3   8128
#define OFF_FA   8320                 // feats ray A: 128 rows x 17
#define OFF_FB   (8320 + 128 * 17)
#define SMEM_FLOATS (8320 + 2 * 128 * 17)
#define SMEM_BYTES (SMEM_FLOATS * 4)

__global__ void __launch_bounds__(128, 3) mlp_kernel(
    const float* __restrict__ delta,
    const float* __restrict__ w_in, const float* __restrict__ w_out,
    const float* __restrict__ rw1, const float* __restrict__ rw2,
    const float* __restrict__ rw3, float4* __restrict__ out, float offset)
{
    extern __shared__ float dsm[];
    __shared__ float wsumA[4], wsumB[4];
    const int t = threadIdx.x;
    for (int i = t; i < 8320; i += 128) {
        float v;
        if (i < 2048)      v = w_in[i];
        else if (i < 3072) v = w_out[i - 2048];
        else if (i < 4032) v = rw1[i - 3072];
        else if (i < 8128) v = rw2[i - 4032];
        else               v = rw3[i - 8128];
        dsm[i] = v;
    }
    __syncthreads();

    const int pA = blockIdx.x * 256 + t;   // ray A
    const int pB = pA + 128;               // ray B
    float* FA = dsm + OFF_FA + t * 17;
    float* FB = dsm + OFF_FB + t * 17;

    // ---- layer 1 (enc @ w_in), enc streamed from g_enc with 1-level prefetch ----
    u64 hAa[32], hAb[32];
    #pragma unroll
    for (int j = 0; j < 32; j++) { hAa[j] = 0ULL; hAb[j] = 0ULL; }

    float2 eA = g_enc[pA], eB = g_enc[pB];
    #pragma unroll 1
    for (int l = 0; l < NLEV; l++) {
        float2 eAn, eBn;
        if (l + 1 < NLEV) {
            eAn = g_enc[(l + 1) * NPTS + pA];
            eBn = g_enc[(l + 1) * NPTS + pB];
        }
        const u64 e0A = pk2(eA.x, eA.x), e1A = pk2(eA.y, eA.y);
        const u64 e0B = pk2(eB.x, eB.x), e1B = pk2(eB.y, eB.y);
        const u64* r0 = (const u64*)(dsm + OFF_WIN + (2 * l) * 64);
        const u64* r1 = r0 + 32;
        #pragma unroll
        for (int j = 0; j < 32; j += 2) {
            const ulonglong2 wv0 = *(const ulonglong2*)(r0 + j);
            const ulonglong2 wv1 = *(const ulonglong2*)(r1 + j);
            hAa[j]     = f2fma(e1A, wv1.x, f2fma(e0A, wv0.x, hAa[j]));
            hAa[j + 1] = f2fma(e1A, wv1.y, f2fma(e0A, wv0.y, hAa[j + 1]));
            hAb[j]     = f2fma(e1B, wv1.x, f2fma(e0B, wv0.x, hAb[j]));
            hAb[j + 1] = f2fma(e1B, wv1.y, f2fma(e0B, wv0.y, hAb[j + 1]));
        }
        eA = eAn; eB = eBn;
    }

    // ---- layer 2: raw = relu(h) @ w_out, two output-halves of 8 ----
    // feats (raw[1..15]) go straight to smem rows; only raw[0] kept in regs.
    float d0A = 0.f, d0B = 0.f;
    #pragma unroll 1
    for (int half = 0; half < 2; half++) {
        u64 a2[4], b2[4];
        #pragma unroll
        for (int j = 0; j < 4; j++) { a2[j] = 0ULL; b2[j] = 0ULL; }
        #pragma unroll
        for (int ic = 0; ic < 32; ic++) {
            float vA0, vA1, vB0, vB1;
            up2(hAa[ic], vA0, vA1); up2(hAb[ic], vB0, vB1);
            const u64 e0A = pk2(fmaxf(vA0, 0.f), fmaxf(vA0, 0.f));
            const u64 e1A = pk2(fmaxf(vA1, 0.f), fmaxf(vA1, 0.f));
            const u64 e0B = pk2(fmaxf(vB0, 0.f), fmaxf(vB0, 0.f));
            const u64 e1B = pk2(fmaxf(vB1, 0.f), fmaxf(vB1, 0.f));
            const u64* r0 = (const u64*)(dsm + OFF_WOUT + (2 * ic) * 16 + half * 8);
            const u64* r1 = r0 + 8;
            #pragma unroll
            for (int j = 0; j < 4; j += 2) {
                const ulonglong2 wv0 = *(const ulonglong2*)(r0 + j);
                const ulonglong2 wv1 = *(const ulonglong2*)(r1 + j);
                a2[j]     = f2fma(e1A, wv1.x, f2fma(e0A, wv0.x, a2[j]));
                a2[j + 1] = f2fma(e1A, wv1.y, f2fma(e0A, wv0.y, a2[j + 1]));
                b2[j]     = f2fma(e1B, wv1.x, f2fma(e0B, wv0.x, b2[j]));
                b2[j + 1] = f2fma(e1B, wv1.y, f2fma(e0B, wv0.y, b2[j + 1]));
            }
        }
        #pragma unroll
        for (int j = 0; j < 4; j++) {
            float vA0, vA1, vB0, vB1;
            up2(a2[j], vA0, vA1); up2(b2[j], vB0, vB1);
            const int o = half * 8 + 2 * j;        // raw indices o, o+1
            if (o == 0) { d0A = vA0; d0B = vB0; }
            else { FA[o - 1] = vA0; FB[o - 1] = vB0; }
            FA[o] = vA1; FB[o] = vB1;              // feats index o+1 -> slot o
        }
    }

    // ---- volume-rendering weights: block-wide exclusive scan per ray ----
    const float ddA = expf(d0A + offset + logf(__ldg(delta + pA)));
    const float ddB = expf(d0B + offset + logf(__ldg(delta + pB)));
    float sA = ddA, sB = ddB;
    const int lane = t & 31, wid = t >> 5;
    #pragma unroll
    for (int o = 1; o < 32; o <<= 1) {
        const float vA = __shfl_up_sync(0xffffffffu, sA, o);
        const float vB = __shfl_up_sync(0xffffffffu, sB, o);
        if (lane >= o) { sA += vA; sB += vB; }
    }
    if (lane == 31) { wsumA[wid] = sA; wsumB[wid] = sB; }
    __syncthreads();
    float prefA = 0.f, prefB = 0.f;
    #pragma unroll
    for (int w = 0; w < 3; w++)
        if (wid > w) { prefA += wsumA[w]; prefB += wsumB[w]; }
    const float exclA = prefA + sA - ddA;
    const float exclB = prefB + sB - ddB;
    const float wgtA = (1.f - expf(-ddA)) * expf(-exclA);
    const float wgtB = (1.f - expf(-ddB)) * expf(-exclB);

    // ---- rgb layer 1: h1 = relu(feats @ rgb_w1), feats from smem ----
    u64 h1A[32], h1B[32];
    #pragma unroll
    for (int j = 0; j < 32; j++) { h1A[j] = 0ULL; h1B[j] = 0ULL; }
    #pragma unroll 1
    for (int i = 0; i < 15; i++) {
        const float fA = FA[i], fB = FB[i];
        const u64 eA2 = pk2(fA, fA);
        const u64 eB2 = pk2(fB, fB);
        const u64* row = (const u64*)(dsm + OFF_W1 + i * 64);
        #pragma unroll
        for (int j = 0; j < 32; j += 2) {
            const ulonglong2 wv = *(const ulonglong2*)(row + j);
            h1A[j]     = f2fma(eA2, wv.x, h1A[j]);
            h1A[j + 1] = f2fma(eA2, wv.y, h1A[j + 1]);
            h1B[j]     = f2fma(eB2, wv.x, h1B[j]);
            h1B[j + 1] = f2fma(eB2, wv.y, h1B[j + 1]);
        }
    }
    #pragma unroll
    for (int j = 0; j < 32; j++) {
        float v0, v1;
        up2(h1A[j], v0, v1); h1A[j] = pk2(fmaxf(v0, 0.f), fmaxf(v1, 0.f));
        up2(h1B[j], v0, v1); h1B[j] = pk2(fmaxf(v0, 0.f), fmaxf(v1, 0.f));
    }

    // ---- rgb layers 2+3, 8 blocks of 8 outputs ----
    float crA = 0.f, cgA = 0.f, cbA = 0.f;
    float crB = 0.f, cgB = 0.f, cbB = 0.f;
    #pragma unroll 1
    for (int ob = 0; ob < 8; ob++) {
        u64 accA[4], accB[4];
        #pragma unroll
        for (int j = 0; j < 4; j++) { accA[j] = 0ULL; accB[j] = 0ULL; }
        #pragma unroll
        for (int ic = 0; ic < 32; ic++) {
            float vA0, vA1, vB0, vB1;
            up2(h1A[ic], vA0, vA1); up2(h1B[ic], vB0, vB1);
            const u64 e0A = pk2(vA0, vA0), e1A = pk2(vA1, vA1);
            const u64 e0B = pk2(vB0, vB0), e1B = pk2(vB1, vB1);
            const u64* r0 = (const u64*)(dsm + OFF_W2 + (2 * ic) * 64 + ob * 8);
            const u64* r1 = r0 + 32;
            #pragma unroll
            for (int j = 0; j < 4; j += 2) {
                const ulonglong2 wv0 = *(const ulonglong2*)(r0 + j);
                const ulonglong2 wv1 = *(const ulonglong2*)(r1 + j);
                accA[j]     = f2fma(e1A, wv1.x, f2fma(e0A, wv0.x, accA[j]));
                accA[j + 1] = f2fma(e1A, wv1.y, f2fma(e0A, wv0.y, accA[j + 1]));
                accB[j]     = f2fma(e1B, wv1.x, f2fma(e0B, wv0.x, accB[j]));
                accB[j + 1] = f2fma(e1B, wv1.y, f2fma(e0B, wv0.y, accB[j + 1]));
            }
        }
        #pragma unroll
        for (int j = 0; j < 4; j++) {
            float vA0, vA1, vB0, vB1;
            up2(accA[j], vA0, vA1); up2(accB[j], vB0, vB1);
            vA0 = fmaxf(vA0, 0.f); vA1 = fmaxf(vA1, 0.f);
            vB0 = fmaxf(vB0, 0.f); vB1 = fmaxf(vB1, 0.f);
            const float* q = dsm + OFF_W3 + (ob * 8 + 2 * j) * 3;
            crA = fmaf(vA0, q[0], fmaf(vA1, q[3], crA));
            cgA = fmaf(vA0, q[1], fmaf(vA1, q[4], cgA));
            cbA = fmaf(vA0, q[2], fmaf(vA1, q[5], cbA));
            crB = fmaf(vB0, q[0], fmaf(vB1, q[3], crB));
            cgB = fmaf(vB0, q[1], fmaf(vB1, q[4], cgB));
            cbB = fmaf(vB0, q[2], fmaf(vB1, q[5], cbB));
        }
    }

    out[pA] = make_float4(wgtA, 1.f / (1.f + expf(-crA)),
                          1.f / (1.f + expf(-cgA)), 1.f / (1.f + expf(-cbA)));
    out[pB] = make_float4(wgtB, 1.f / (1.f + expf(-crB)),
                          1.f / (1.f + expf(-cgB)), 1.f / (1.f + expf(-cbB)));
}

// pads FIRST: harness has 2 internal launches before ours, so global launch
// idx 5 (ncu -s 5 -c 1) = our 4th launch = encode_kernel.
__global__ void pad_kernel() {}

extern "C" void kernel_launch(void* const* d_in, const int* in_sizes, int n_in,
                              void* d_out, int out_size)
{
    const float* xyz   = (const float*)d_in[0];
    const float* delta = (const float*)d_in[1];
    const float* table = (const float*)d_in[2];
    const float* w_in  = (const float*)d_in[3];
    const float* w_out = (const float*)d_in[4];
    const float* rw1   = (const float*)d_in[5];
    const float* rw2   = (const float*)d_in[6];
    const float* rw3   = (const float*)d_in[7];
    float4* out = (float4*)d_out;

    Consts cc;
    const double scale = exp((log(4096.0) - log(16.0)) / 15.0);
    for (int l = 0; l < NLEV; l++)
        cc.res[l] = (float)floor(16.0 * pow(scale, (double)l));
    const float offset = (float)(log(log(1.0 / 0.99)) - log(6.0 - 2.0) - 0.5);

    static int smem_set = 0;
    if (!smem_set) {
        cudaFuncSetAttribute(mlp_kernel,
                             cudaFuncAttributeMaxDynamicSharedMemorySize,
                             SMEM_BYTES);
        smem_set = 1;
    }

    pad_kernel<<<1, 1>>>();
    pad_kernel<<<1, 1>>>();
    pad_kernel<<<1, 1>>>();
    encode_kernel<<<NPTS / 256, 256>>>(xyz, table, cc);
    mlp_kernel<<<NPTS / 256, 128, SMEM_BYTES>>>(delta, w_in, w_out,
                                                rw1, rw2, rw3, out, offset);
}

// round 9
// speedup vs baseline: 1.7603x; 1.2015x over previous
#include <cuda_runtime.h>
#include <math.h>

typedef unsigned int u32;
typedef unsigned long long u64;

#define NLEV 16
#define HSIZE (1u << 19)
#define HMASK (HSIZE - 1u)
#define NPTS (4096 * 128)

struct Consts { float res[NLEV]; };

// 67 MB scratch: per-level encoded features, feat-major for coalescing.
__device__ float2 g_enc[NLEV * NPTS];

// ---------- packed f32x2 helpers ----------
__device__ __forceinline__ u64 pk2(float a, float b) {
    u64 r; asm("mov.b64 %0,{%1,%2};" : "=l"(r) : "f"(a), "f"(b)); return r;
}
__device__ __forceinline__ void up2(u64 v, float& a, float& b) {
    asm("mov.b64 {%0,%1},%2;" : "=f"(a), "=f"(b) : "l"(v));
}
__device__ __forceinline__ u64 f2fma(u64 a, u64 b, u64 c) {
    u64 d; asm("fma.rn.f32x2 %0,%1,%2,%3;" : "=l"(d) : "l"(a), "l"(b), "l"(c)); return d;
}

// ===================== K1: encode (gather-bound) =====================

__device__ __forceinline__ void level_fetch(
    float px, float py, float pz, float r,
    const float2* __restrict__ tab,
    float2 tv[8], float& ax, float& ay, float& az)
{
    const float X = px * r, Y = py * r, Z = pz * r;
    const float fx = floorf(X), fy = floorf(Y), fz = floorf(Z);
    ax = X - fx; ay = Y - fy; az = Z - fz;
    const u32 ix = (u32)fx, iy = (u32)fy, iz = (u32)fz;
    const u32 hx0 = ix, hx1 = ix + 1u;
    const u32 hy0 = iy * 2654435761u, hy1 = hy0 + 2654435761u;
    const u32 hz0 = iz * 805459861u,  hz1 = hz0 + 805459861u;
    #pragma unroll
    for (int c = 0; c < 8; c++) {
        const u32 hx = (c & 4) ? hx1 : hx0;
        const u32 hy = (c & 2) ? hy1 : hy0;
        const u32 hz = (c & 1) ? hz1 : hz0;
        tv[c] = __ldg(tab + ((hx ^ hy ^ hz) & HMASK));
    }
}

__global__ void __launch_bounds__(256, 3) encode_kernel(
    const float* __restrict__ xyz, const float* __restrict__ table, Consts cc)
{
    const int p = blockIdx.x * 256 + threadIdx.x;
    const float px = __ldg(xyz + 3 * p);
    const float py = __ldg(xyz + 3 * p + 1);
    const float pz = __ldg(xyz + 3 * p + 2);

    float2 tvb[2][8];
    float fr[2][3];
    level_fetch(px, py, pz, cc.res[0], (const float2*)table,
                tvb[0], fr[0][0], fr[0][1], fr[0][2]);

    #pragma unroll 2
    for (int l = 0; l < NLEV; l++) {
        const int cur = l & 1, nxt = cur ^ 1;
        if (l + 1 < NLEV)
            level_fetch(px, py, pz, cc.res[l + 1],
                        (const float2*)table + (size_t)(l + 1) * HSIZE,
                        tvb[nxt], fr[nxt][0], fr[nxt][1], fr[nxt][2]);
        const float ax = fr[cur][0], ay = fr[cur][1], az = fr[cur][2];
        const float bx = 1.f - ax, by = 1.f - ay, bz = 1.f - az;
        float a0 = 0.f, a1 = 0.f;
        #pragma unroll
        for (int c = 0; c < 8; c++) {
            const float w = ((c & 4) ? ax : bx) * ((c & 2) ? ay : by) * ((c & 1) ? az : bz);
            a0 = fmaf(w, tvb[cur][c].x, a0);
            a1 = fmaf(w, tvb[cur][c].y, a1);
        }
        g_enc[l * NPTS + p] = make_float2(a0, a1);
    }
}

// ===================== K2: MLP + volrend (FMA/LDS-bound) =====================

#define OFF_WIN  0
#define OFF_WOUT 2048
#define OFF_W1   3072
#define OFF_W2   4032
#define OFF_W3   8128
#define OFF_FA   8320                 // feats ray A: 128 rows x 17
#define OFF_FB   (8320 + 128 * 17)
#define SMEM_FLOATS (8320 + 2 * 128 * 17)
#define SMEM_BYTES (SMEM_FLOATS * 4)

__global__ void __launch_bounds__(128, 3) mlp_kernel(
    const float* __restrict__ delta,
    const float* __restrict__ w_in, const float* __restrict__ w_out,
    const float* __restrict__ rw1, const float* __restrict__ rw2,
    const float* __restrict__ rw3, float4* __restrict__ out, float offset)
{
    extern __shared__ float dsm[];
    __shared__ float wsumA[4], wsumB[4];
    const int t = threadIdx.x;
    for (int i = t; i < 8320; i += 128) {
        float v;
        if (i < 2048)      v = w_in[i];
        else if (i < 3072) v = w_out[i - 2048];
        else if (i < 4032) v = rw1[i - 3072];
        else if (i < 8128) v = rw2[i - 4032];
        else               v = rw3[i - 8128];
        dsm[i] = v;
    }
    __syncthreads();

    const int pA = blockIdx.x * 256 + t;   // ray A
    const int pB = pA + 128;               // ray B
    float* FA = dsm + OFF_FA + t * 17;
    float* FB = dsm + OFF_FB + t * 17;

    // ---- density MLP: two passes over hidden-halves, low register peak ----
    // raw accumulators live across both halves (16 outputs, packed).
    u64 rA2[8], rB2[8];
    #pragma unroll
    for (int j = 0; j < 8; j++) { rA2[j] = 0ULL; rB2[j] = 0ULL; }

    #pragma unroll 1
    for (int half = 0; half < 2; half++) {
        // layer 1: h[half*32 .. half*32+32) for both points
        u64 hA[16], hB[16];
        #pragma unroll
        for (int j = 0; j < 16; j++) { hA[j] = 0ULL; hB[j] = 0ULL; }

        #pragma unroll 1
        for (int l = 0; l < NLEV; l++) {
            const float2 eA = g_enc[l * NPTS + pA];
            const float2 eB = g_enc[l * NPTS + pB];
            const u64 e0A = pk2(eA.x, eA.x), e1A = pk2(eA.y, eA.y);
            const u64 e0B = pk2(eB.x, eB.x), e1B = pk2(eB.y, eB.y);
            const u64* r0 = (const u64*)(dsm + OFF_WIN + (2 * l) * 64 + half * 32);
            const u64* r1 = r0 + 32;   // next enc row (64 floats = 32 u64)
            #pragma unroll
            for (int j = 0; j < 16; j += 2) {
                const ulonglong2 wv0 = *(const ulonglong2*)(r0 + j);
                const ulonglong2 wv1 = *(const ulonglong2*)(r1 + j);
                hA[j]     = f2fma(e1A, wv1.x, f2fma(e0A, wv0.x, hA[j]));
                hA[j + 1] = f2fma(e1A, wv1.y, f2fma(e0A, wv0.y, hA[j + 1]));
                hB[j]     = f2fma(e1B, wv1.x, f2fma(e0B, wv0.x, hB[j]));
                hB[j + 1] = f2fma(e1B, wv1.y, f2fma(e0B, wv0.y, hB[j + 1]));
            }
        }

        // wout partial: relu(h-half) @ w_out rows [half*32, half*32+32)
        #pragma unroll
        for (int ic = 0; ic < 16; ic++) {
            float vA0, vA1, vB0, vB1;
            up2(hA[ic], vA0, vA1); up2(hB[ic], vB0, vB1);
            const u64 e0A = pk2(fmaxf(vA0, 0.f), fmaxf(vA0, 0.f));
            const u64 e1A = pk2(fmaxf(vA1, 0.f), fmaxf(vA1, 0.f));
            const u64 e0B = pk2(fmaxf(vB0, 0.f), fmaxf(vB0, 0.f));
            const u64 e1B = pk2(fmaxf(vB1, 0.f), fmaxf(vB1, 0.f));
            const u64* r0 = (const u64*)(dsm + OFF_WOUT + (half * 32 + 2 * ic) * 16);
            const u64* r1 = r0 + 8;
            #pragma unroll
            for (int j = 0; j < 8; j += 2) {
                const ulonglong2 wv0 = *(const ulonglong2*)(r0 + j);
                const ulonglong2 wv1 = *(const ulonglong2*)(r1 + j);
                rA2[j]     = f2fma(e1A, wv1.x, f2fma(e0A, wv0.x, rA2[j]));
                rA2[j + 1] = f2fma(e1A, wv1.y, f2fma(e0A, wv0.y, rA2[j + 1]));
                rB2[j]     = f2fma(e1B, wv1.x, f2fma(e0B, wv0.x, rB2[j]));
                rB2[j + 1] = f2fma(e1B, wv1.y, f2fma(e0B, wv0.y, rB2[j + 1]));
            }
        }
    }

    // unpack raw: raw[0] -> density; raw[1..15] -> feats in smem rows
    float d0A = 0.f, d0B = 0.f;
    #pragma unroll
    for (int j = 0; j < 8; j++) {
        float vA0, vA1, vB0, vB1;
        up2(rA2[j], vA0, vA1); up2(rB2[j], vB0, vB1);
        const int o = 2 * j;
        if (o == 0) { d0A = vA0; d0B = vB0; }
        else { FA[o - 1] = vA0; FB[o - 1] = vB0; }
        FA[o] = vA1; FB[o] = vB1;    // feats index o+1 -> slot o
    }

    // ---- volume-rendering weights: block-wide exclusive scan per ray ----
    const float ddA = expf(d0A + offset + logf(__ldg(delta + pA)));
    const float ddB = expf(d0B + offset + logf(__ldg(delta + pB)));
    float sA = ddA, sB = ddB;
    const int lane = t & 31, wid = t >> 5;
    #pragma unroll
    for (int o = 1; o < 32; o <<= 1) {
        const float vA = __shfl_up_sync(0xffffffffu, sA, o);
        const float vB = __shfl_up_sync(0xffffffffu, sB, o);
        if (lane >= o) { sA += vA; sB += vB; }
    }
    if (lane == 31) { wsumA[wid] = sA; wsumB[wid] = sB; }
    __syncthreads();
    float prefA = 0.f, prefB = 0.f;
    #pragma unroll
    for (int w = 0; w < 3; w++)
        if (wid > w) { prefA += wsumA[w]; prefB += wsumB[w]; }
    const float exclA = prefA + sA - ddA;
    const float exclB = prefB + sB - ddB;
    const float wgtA = (1.f - expf(-ddA)) * expf(-exclA);
    const float wgtB = (1.f - expf(-ddB)) * expf(-exclB);

    // ---- rgb layer 1: h1 = relu(feats @ rgb_w1), feats from smem ----
    u64 h1A[32], h1B[32];
    #pragma unroll
    for (int j = 0; j < 32; j++) { h1A[j] = 0ULL; h1B[j] = 0ULL; }
    #pragma unroll 1
    for (int i = 0; i < 15; i++) {
        const float fA = FA[i], fB = FB[i];
        const u64 eA2 = pk2(fA, fA);
        const u64 eB2 = pk2(fB, fB);
        const u64* row = (const u64*)(dsm + OFF_W1 + i * 64);
        #pragma unroll
        for (int j = 0; j < 32; j += 2) {
            const ulonglong2 wv = *(const ulonglong2*)(row + j);
            h1A[j]     = f2fma(eA2, wv.x, h1A[j]);
            h1A[j + 1] = f2fma(eA2, wv.y, h1A[j + 1]);
            h1B[j]     = f2fma(eB2, wv.x, h1B[j]);
            h1B[j + 1] = f2fma(eB2, wv.y, h1B[j + 1]);
        }
    }
    #pragma unroll
    for (int j = 0; j < 32; j++) {
        float v0, v1;
        up2(h1A[j], v0, v1); h1A[j] = pk2(fmaxf(v0, 0.f), fmaxf(v1, 0.f));
        up2(h1B[j], v0, v1); h1B[j] = pk2(fmaxf(v0, 0.f), fmaxf(v1, 0.f));
    }

    // ---- rgb layers 2+3, 8 blocks of 8 outputs ----
    float crA = 0.f, cgA = 0.f, cbA = 0.f;
    float crB = 0.f, cgB = 0.f, cbB = 0.f;
    #pragma unroll 1
    for (int ob = 0; ob < 8; ob++) {
        u64 accA[4], accB[4];
        #pragma unroll
        for (int j = 0; j < 4; j++) { accA[j] = 0ULL; accB[j] = 0ULL; }
        #pragma unroll
        for (int ic = 0; ic < 32; ic++) {
            float vA0, vA1, vB0, vB1;
            up2(h1A[ic], vA0, vA1); up2(h1B[ic], vB0, vB1);
            const u64 e0A = pk2(vA0, vA0), e1A = pk2(vA1, vA1);
            const u64 e0B = pk2(vB0, vB0), e1B = pk2(vB1, vB1);
            const u64* r0 = (const u64*)(dsm + OFF_W2 + (2 * ic) * 64 + ob * 8);
            const u64* r1 = r0 + 32;
            #pragma unroll
            for (int j = 0; j < 4; j += 2) {
                const ulonglong2 wv0 = *(const ulonglong2*)(r0 + j);
                const ulonglong2 wv1 = *(const ulonglong2*)(r1 + j);
                accA[j]     = f2fma(e1A, wv1.x, f2fma(e0A, wv0.x, accA[j]));
                accA[j + 1] = f2fma(e1A, wv1.y, f2fma(e0A, wv0.y, accA[j + 1]));
                accB[j]     = f2fma(e1B, wv1.x, f2fma(e0B, wv0.x, accB[j]));
                accB[j + 1] = f2fma(e1B, wv1.y, f2fma(e0B, wv0.y, accB[j + 1]));
            }
        }
        #pragma unroll
        for (int j = 0; j < 4; j++) {
            float vA0, vA1, vB0, vB1;
            up2(accA[j], vA0, vA1); up2(accB[j], vB0, vB1);
            vA0 = fmaxf(vA0, 0.f); vA1 = fmaxf(vA1, 0.f);
            vB0 = fmaxf(vB0, 0.f); vB1 = fmaxf(vB1, 0.f);
            const float* q = dsm + OFF_W3 + (ob * 8 + 2 * j) * 3;
            crA = fmaf(vA0, q[0], fmaf(vA1, q[3], crA));
            cgA = fmaf(vA0, q[1], fmaf(vA1, q[4], cgA));
            cbA = fmaf(vA0, q[2], fmaf(vA1, q[5], cbA));
            crB = fmaf(vB0, q[0], fmaf(vB1, q[3], crB));
            cgB = fmaf(vB0, q[1], fmaf(vB1, q[4], cgB));
            cbB = fmaf(vB0, q[2], fmaf(vB1, q[5], cbB));
        }
    }

    out[pA] = make_float4(wgtA, 1.f / (1.f + expf(-crA)),
                          1.f / (1.f + expf(-cgA)), 1.f / (1.f + expf(-cbA)));
    out[pB] = make_float4(wgtB, 1.f / (1.f + expf(-crB)),
                          1.f / (1.f + expf(-cgB)), 1.f / (1.f + expf(-cbB)));
}

// launch order pad,pad,encode,mlp: harness has 2 internal launches first, so
// global launch idx 5 (ncu -s 5 -c 1) = mlp_kernel (profiling K2 this round).
__global__ void pad_kernel() {}

extern "C" void kernel_launch(void* const* d_in, const int* in_sizes, int n_in,
                              void* d_out, int out_size)
{
    const float* xyz   = (const float*)d_in[0];
    const float* delta = (const float*)d_in[1];
    const float* table = (const float*)d_in[2];
    const float* w_in  = (const float*)d_in[3];
    const float* w_out = (const float*)d_in[4];
    const float* rw1   = (const float*)d_in[5];
    const float* rw2   = (const float*)d_in[6];
    const float* rw3   = (const float*)d_in[7];
    float4* out = (float4*)d_out;

    Consts cc;
    const double scale = exp((log(4096.0) - log(16.0)) / 15.0);
    for (int l = 0; l < NLEV; l++)
        cc.res[l] = (float)floor(16.0 * pow(scale, (double)l));
    const float offset = (float)(log(log(1.0 / 0.99)) - log(6.0 - 2.0) - 0.5);

    static int smem_set = 0;
    if (!smem_set) {
        cudaFuncSetAttribute(mlp_kernel,
                             cudaFuncAttributeMaxDynamicSharedMemorySize,
                             SMEM_BYTES);
        smem_set = 1;
    }

    pad_kernel<<<1, 1>>>();
    pad_kernel<<<1, 1>>>();
    encode_kernel<<<NPTS / 256, 256>>>(xyz, table, cc);
    mlp_kernel<<<NPTS / 256, 128, SMEM_BYTES>>>(delta, w_in, w_out,
                                                rw1, rw2, rw3, out, offset);
}